// round 4
// baseline (speedup 1.0000x reference)
#include <cuda_runtime.h>
#include <cuda_fp16.h>
#include <cstdint>

// Problem constants (match reference)
#define BATCH 4
#define CHANNELS 64
#define IMG 512
#define HW (IMG * IMG)
#define GRID_RES 64

// 128 MB scratch: pixel_features transposed to NHWC (B, H, W, C) in fp16.
__device__ __half g_nhwc[(size_t)BATCH * HW * CHANNELS];

// ---------------------------------------------------------------------------
// Kernel 1: NCHW fp32 -> NHWC fp16 transpose (64x64 smem tile).
// ---------------------------------------------------------------------------
__global__ void __launch_bounds__(256) transpose_nchw_nhwc(const float* __restrict__ in) {
    __shared__ float tile[64][65];

    int block = blockIdx.x;
    int b = block >> 12;                 // HW/64 = 4096 blocks per batch
    int hwbase = (block & 4095) << 6;    // *64

    const float* src = in + (size_t)b * CHANNELS * HW;
    int tid = threadIdx.x;

    int c0 = tid >> 4;            // 0..15
    int x4 = (tid & 15) << 2;     // 0..60
#pragma unroll
    for (int cc = c0; cc < 64; cc += 16) {
        float4 v = *(const float4*)(src + (size_t)cc * HW + hwbase + x4);
        tile[cc][x4 + 0] = v.x;
        tile[cc][x4 + 1] = v.y;
        tile[cc][x4 + 2] = v.z;
        tile[cc][x4 + 3] = v.w;
    }
    __syncthreads();

    int h0 = tid >> 4;            // 0..15
    int c4 = (tid & 15) << 2;     // 0..60
    __half* dst = g_nhwc + ((size_t)b * HW + hwbase) * CHANNELS;
#pragma unroll
    for (int h = h0; h < 64; h += 16) {
        __half2 lo = __floats2half2_rn(tile[c4 + 0][h], tile[c4 + 1][h]);
        __half2 hi = __floats2half2_rn(tile[c4 + 2][h], tile[c4 + 3][h]);
        uint2 v;
        v.x = *(const unsigned int*)&lo;
        v.y = *(const unsigned int*)&hi;
        *(uint2*)(dst + (size_t)h * CHANNELS + c4) = v;
    }
}

// ---------------------------------------------------------------------------
// Kernel 2: two-phase project + gather, templated on "block is full".
// FULL=true path: no bounds checks anywhere -> straight-line unrolled gather
// so ptxas can batch LDGs across iterations (high MLP).
// ---------------------------------------------------------------------------
template <bool FULL>
__global__ void __launch_bounds__(256) project_gather(
    const int* __restrict__ coords,
    const float* __restrict__ Km,
    const float* __restrict__ Pm,
    float* __restrict__ out,
    int N)
{
    __shared__ float4 s_pt[256];    // {i_f, j_f, di, dj}
    __shared__ int    s_base[256];  // batch * HW * CHANNELS
    __shared__ float  sK[9];
    __shared__ float  sP[16];

    int tid = threadIdx.x;
    if (tid < 9)       sK[tid] = Km[tid];
    else if (tid < 25) sP[tid - 9] = Pm[tid - 9];
    __syncthreads();

    int base = blockIdx.x << 8;
    int p = base + tid;

    // ---- Phase 1: projection (one thread per point) ----
    if (FULL || p < N) {
        int4 cd = __ldcs((const int4*)(coords + (size_t)p * 4));

        const float scale = 2.0f / (float)(GRID_RES - 1);
        float wx = (float)cd.y * scale - 1.0f;
        float wy = (float)cd.z * scale - 1.0f;
        float wz = (float)cd.w * scale - 1.0f;

        float camx = sP[0]  * wx + sP[1]  * wy + sP[2]  * wz + sP[3];
        float camy = sP[4]  * wx + sP[5]  * wy + sP[6]  * wz + sP[7];
        float camz = sP[8]  * wx + sP[9]  * wy + sP[10] * wz + sP[11];
        float camw = sP[12] * wx + sP[13] * wy + sP[14] * wz + sP[15];
        float invw4 = 1.0f / camw;
        camx *= invw4; camy *= invw4; camz *= invw4;

        float u = sK[0] * camx + sK[1] * camy + sK[2] * camz;
        float v = sK[3] * camx + sK[4] * camy + sK[5] * camz;
        float w = sK[6] * camx + sK[7] * camy + sK[8] * camz;
        float invw = 1.0f / w;
        float x_real = u * invw;   // -> j (W)
        float y_real = v * invw;   // -> i (H)

        __stcs(out + (size_t)N * CHANNELS + p, camz);

        float i_f = floorf(y_real);
        float j_f = floorf(x_real);
        s_pt[tid] = make_float4(i_f, j_f, y_real - i_f, x_real - j_f);
        s_base[tid] = cd.x * (HW * CHANNELS);
    }
    __syncthreads();

    // ---- Phase 2: gather (8 lanes per point, 8 points per lane-group) ----
    int lane = tid & 7;
    int grp  = tid >> 3;
    int coff = lane << 3;           // 8 fp16 channels per lane
    int npts = FULL ? 256 : (N - base);

    // Prefetch all point records into registers first.
    float4 pt[8];
    int    fb[8];
#pragma unroll
    for (int it = 0; it < 8; it++) {
        int pp = grp + (it << 5);
        if (FULL || pp < npts) {
            pt[it] = s_pt[pp];
            fb[it] = s_base[pp];
        }
    }

#pragma unroll
    for (int it = 0; it < 8; it++) {
        int pp = grp + (it << 5);
        if (!FULL && pp >= npts) break;

        int ii = (int)pt[it].x;
        int jj = (int)pt[it].y;
        int i0 = min(max(ii, 0), IMG - 1);
        int i1 = min(max(ii + 1, 0), IMG - 1);
        int j0 = min(max(jj, 0), IMG - 1);
        int j1 = min(max(jj + 1, 0), IMG - 1);
        float di = pt[it].z;
        float dj = pt[it].w;

        const __half* bp = g_nhwc + fb[it] + coff;
        int r0 = i0 << 15;
        int r1 = i1 << 15;
        int c0 = j0 << 6;
        int c1 = j1 << 6;

        uint4 a00 = *(const uint4*)(bp + r0 + c0);
        uint4 a01 = *(const uint4*)(bp + r0 + c1);
        uint4 a10 = *(const uint4*)(bp + r1 + c0);
        uint4 a11 = *(const uint4*)(bp + r1 + c1);

        float w00 = (1.0f - di) * (1.0f - dj);
        float w10 = di * (1.0f - dj);
        float w01 = (1.0f - di) * dj;
        float w11 = di * dj;

        const unsigned int* u00 = (const unsigned int*)&a00;
        const unsigned int* u01 = (const unsigned int*)&a01;
        const unsigned int* u10 = (const unsigned int*)&a10;
        const unsigned int* u11 = (const unsigned int*)&a11;

        float res[8];
#pragma unroll
        for (int k = 0; k < 4; k++) {
            float2 f00 = __half22float2(*(const __half2*)&u00[k]);
            float2 f01 = __half22float2(*(const __half2*)&u01[k]);
            float2 f10 = __half22float2(*(const __half2*)&u10[k]);
            float2 f11 = __half22float2(*(const __half2*)&u11[k]);
            res[2*k]   = w00 * f00.x + w10 * f10.x + w01 * f01.x + w11 * f11.x;
            res[2*k+1] = w00 * f00.y + w10 * f10.y + w01 * f01.y + w11 * f11.y;
        }

        float* op = out + ((size_t)(base + pp) << 6) + coff;
        __stcs((float4*)op,     make_float4(res[0], res[1], res[2], res[3]));
        __stcs((float4*)op + 1, make_float4(res[4], res[5], res[6], res[7]));
    }
}

extern "C" void kernel_launch(void* const* d_in, const int* in_sizes, int n_in,
                              void* d_out, int out_size) {
    const int*   coords = (const int*)d_in[0];
    const float* feats  = (const float*)d_in[1];
    const float* Km     = (const float*)d_in[2];
    const float* Pm     = (const float*)d_in[3];
    float* out = (float*)d_out;

    int N = in_sizes[0] / 4;

    transpose_nchw_nhwc<<<BATCH * (HW / 64), 256>>>(feats);

    if ((N & 255) == 0) {
        project_gather<true><<<N >> 8, 256>>>(coords, Km, Pm, out, N);
    } else {
        project_gather<false><<<(N + 255) / 256, 256>>>(coords, Km, Pm, out, N);
    }
}